// round 2
// baseline (speedup 1.0000x reference)
#include <cuda_runtime.h>
#include <math.h>

// Problem dims
#define T_STEPS 512
#define B_SIZE  64
#define D_DIM   1024
#define L_DIM   1024
#define G4      4096          // 4*L
#define BL      65536         // B*L
#define BG      262144        // B*4L
#define NBLK    128           // persistent CTAs (<=148 -> all resident, barrier safe)

// ---------------- scratch (no allocations allowed) ----------------
__device__ float g_W[2048u * 4096u];                 // packed [k][j]; k<1024: x-part, k>=1024: h-part
__device__ float g_bias[G4];
__device__ float g_Xg[(size_t)T_STEPS * BG];         // precomputed x-projection + bias
__device__ float g_h[2][BL];                         // double-buffered hidden state
__device__ float g_c[BL];                            // cell state
__device__ float g_part[8][BG];                      // K-split partial sums for recurrent GEMM

// barrier state
__device__ unsigned int g_bar_count = 0;
__device__ volatile unsigned int g_bar_gen = 0;

// ---------------- packed f32x2 helpers (Blackwell) ----------------
__device__ __forceinline__ unsigned long long pack2(float lo, float hi) {
    unsigned long long r;
    asm("mov.b64 %0, {%1, %2};" : "=l"(r) : "f"(lo), "f"(hi));
    return r;
}
__device__ __forceinline__ void fma2(unsigned long long& d, unsigned long long a, unsigned long long b) {
    asm("fma.rn.f32x2 %0, %1, %2, %0;" : "+l"(d) : "l"(a), "l"(b));
}
__device__ __forceinline__ float2 unpack2(unsigned long long v) {
    float2 r;
    asm("mov.b64 {%0, %1}, %2;" : "=f"(r.x), "=f"(r.y) : "l"(v));
    return r;
}

__device__ __forceinline__ float sigm_f(float x) {
    return __fdividef(1.f, 1.f + __expf(-x));
}
__device__ __forceinline__ float tanh_f(float x) {
    return __fdividef(2.f, 1.f + __expf(-2.f * x)) - 1.f;
}

// ---------------- grid-wide spin barrier ----------------
__device__ __forceinline__ void grid_sync() {
    __threadfence();
    __syncthreads();
    if (threadIdx.x == 0) {
        unsigned int gen = g_bar_gen;
        if (atomicAdd(&g_bar_count, 1u) == NBLK - 1) {
            g_bar_count = 0;
            __threadfence();
            g_bar_gen = gen + 1;
        } else {
            while (g_bar_gen == gen) { __nanosleep(32); }
        }
    }
    __syncthreads();
    __threadfence();
}

// ---------------- weight pack + init ----------------
__global__ void pack_weights(const float* __restrict__ Wf, const float* __restrict__ Wi,
                             const float* __restrict__ Wo, const float* __restrict__ Wg,
                             const float* __restrict__ bf, const float* __restrict__ bi,
                             const float* __restrict__ bo, const float* __restrict__ bg) {
    int stride = gridDim.x * blockDim.x;
    int tid0 = blockIdx.x * blockDim.x + threadIdx.x;
    const int total = 2048 * 4096;
    for (int i = tid0; i < total; i += stride) {
        int k = i >> 12;
        int j = i & 4095;
        int gate = j >> 10;
        int l = j & 1023;
        const float* W = (gate == 0) ? Wf : (gate == 1) ? Wi : (gate == 2) ? Wo : Wg;
        g_W[(size_t)k * 4096 + j] = W[k * 1024 + l];
    }
    for (int i = tid0; i < G4; i += stride) {
        int gate = i >> 10;
        int l = i & 1023;
        const float* b = (gate == 0) ? bf : (gate == 1) ? bi : (gate == 2) ? bo : bg;
        g_bias[i] = b[l];
    }
}

__global__ void init_state() {
    int i = blockIdx.x * blockDim.x + threadIdx.x;
    if (i < BL) {
        g_h[0][i] = 0.f;
        g_h[1][i] = 0.f;
        g_c[i] = 0.f;
    }
}

// ---------------- big precompute GEMM: Xg = x @ Wx + bias ----------------
// C[32768, 4096] = A[32768, 1024] * g_W[0:1024, :]
// 128x128 tile, BK=8, 256 threads, 8x8 per thread, packed f32x2 math.
__global__ __launch_bounds__(256) void gemm_x(const float* __restrict__ A) {
    const int bx = blockIdx.x;   // N tiles (32)
    const int by = blockIdx.y;   // M tiles (256)
    __shared__ float As[8][128];
    __shared__ float Bs[8][128];

    const int tid = threadIdx.x;
    const int tx = tid & 15;
    const int ty = tid >> 4;

    const int a_row = tid >> 1;
    const int a_col = (tid & 1) * 4;
    const int b_row = tid >> 5;
    const int b_col = (tid & 31) * 4;

    const float* Aptr = A + (size_t)(by * 128) * 1024;
    const float* Bptr = g_W + (size_t)bx * 128;

    unsigned long long acc[8][4];
#pragma unroll
    for (int m = 0; m < 8; m++)
#pragma unroll
        for (int n = 0; n < 4; n++) acc[m][n] = 0ull;

    for (int k0 = 0; k0 < 1024; k0 += 8) {
        float4 av = *(const float4*)(Aptr + (size_t)a_row * 1024 + k0 + a_col);
        As[a_col + 0][a_row] = av.x;
        As[a_col + 1][a_row] = av.y;
        As[a_col + 2][a_row] = av.z;
        As[a_col + 3][a_row] = av.w;
        *(float4*)&Bs[b_row][b_col] =
            *(const float4*)(Bptr + (size_t)(k0 + b_row) * 4096 + b_col);
        __syncthreads();
#pragma unroll
        for (int kk = 0; kk < 8; kk++) {
            float4 a0 = *(const float4*)&As[kk][ty * 8];
            float4 a1 = *(const float4*)&As[kk][ty * 8 + 4];
            ulonglong2 bA = *(const ulonglong2*)&Bs[kk][tx * 8];
            ulonglong2 bB = *(const ulonglong2*)&Bs[kk][tx * 8 + 4];
            unsigned long long b[4] = {bA.x, bA.y, bB.x, bB.y};
            float a[8] = {a0.x, a0.y, a0.z, a0.w, a1.x, a1.y, a1.z, a1.w};
#pragma unroll
            for (int m = 0; m < 8; m++) {
                unsigned long long am = pack2(a[m], a[m]);
                fma2(acc[m][0], am, b[0]);
                fma2(acc[m][1], am, b[1]);
                fma2(acc[m][2], am, b[2]);
                fma2(acc[m][3], am, b[3]);
            }
        }
        __syncthreads();
    }

#pragma unroll
    for (int m = 0; m < 8; m++) {
        int row = by * 128 + ty * 8 + m;
        int col = bx * 128 + tx * 8;
        size_t base = (size_t)row * 4096 + col;
        float2 v0 = unpack2(acc[m][0]), v1 = unpack2(acc[m][1]);
        float2 v2 = unpack2(acc[m][2]), v3 = unpack2(acc[m][3]);
        float4 w0 = {v0.x + g_bias[col + 0], v0.y + g_bias[col + 1],
                     v1.x + g_bias[col + 2], v1.y + g_bias[col + 3]};
        float4 w1 = {v2.x + g_bias[col + 4], v2.y + g_bias[col + 5],
                     v3.x + g_bias[col + 6], v3.y + g_bias[col + 7]};
        *(float4*)&g_Xg[base + 0] = w0;
        *(float4*)&g_Xg[base + 4] = w1;
    }
}

// ---------------- persistent recurrent scan ----------------
// 128 CTAs x 256 threads. Per step:
//   phase1: gates partials = h @ Wh  (16 col-tiles of 256 x 8 K-splits of 128)
//   phase2: reduce partials + Xg, apply LSTM nonlinearity, write h/c/out
// Two grid barriers per step.
__global__ __launch_bounds__(256, 1) void lstm_scan(float* __restrict__ out) {
    __shared__ float Hs[16][68];    // padded, 16B-aligned rows
    __shared__ float Ws[16][256];

    const int tid = threadIdx.x;
    const int bx = blockIdx.x;
    const int ct = bx & 15;         // column tile: cols [ct*256, ct*256+256)
    const int ks = bx >> 4;         // K split:   k in [ks*128, ks*128+128)
    const int kbase = ks * 128;
    const int ty = tid >> 5;        // 0..7  -> 8 rows each
    const int tx = tid & 31;        // 0..31 -> 8 cols each
    const int h_row = tid >> 2;     // 0..63
    const int h_kc = (tid & 3) * 4; // 0,4,8,12

    for (int t = 0; t < T_STEPS; t++) {
        const int cur = t & 1;
        const float* __restrict__ h = g_h[cur];

        unsigned long long acc[8][4];
#pragma unroll
        for (int m = 0; m < 8; m++)
#pragma unroll
            for (int n = 0; n < 4; n++) acc[m][n] = 0ull;

        for (int k0 = 0; k0 < 128; k0 += 16) {
            // H tile: 64 rows x 16 k, transposed into Hs
            float4 hv = *(const float4*)(h + (size_t)h_row * 1024 + kbase + k0 + h_kc);
            Hs[h_kc + 0][h_row] = hv.x;
            Hs[h_kc + 1][h_row] = hv.y;
            Hs[h_kc + 2][h_row] = hv.z;
            Hs[h_kc + 3][h_row] = hv.w;
            // W tile: 16 k x 256 cols
#pragma unroll
            for (int r = 0; r < 4; r++) {
                int idx = tid + r * 256;
                int kr = idx >> 6;
                int cc = (idx & 63) * 4;
                *(float4*)&Ws[kr][cc] =
                    *(const float4*)(g_W + (size_t)(1024 + kbase + k0 + kr) * 4096 + ct * 256 + cc);
            }
            __syncthreads();
#pragma unroll
            for (int kk = 0; kk < 16; kk++) {
                float4 a0 = *(const float4*)&Hs[kk][ty * 8];
                float4 a1 = *(const float4*)&Hs[kk][ty * 8 + 4];
                ulonglong2 bA = *(const ulonglong2*)&Ws[kk][tx * 8];
                ulonglong2 bB = *(const ulonglong2*)&Ws[kk][tx * 8 + 4];
                unsigned long long b[4] = {bA.x, bA.y, bB.x, bB.y};
                float a[8] = {a0.x, a0.y, a0.z, a0.w, a1.x, a1.y, a1.z, a1.w};
#pragma unroll
                for (int m = 0; m < 8; m++) {
                    unsigned long long am = pack2(a[m], a[m]);
                    fma2(acc[m][0], am, b[0]);
                    fma2(acc[m][1], am, b[1]);
                    fma2(acc[m][2], am, b[2]);
                    fma2(acc[m][3], am, b[3]);
                }
            }
            __syncthreads();
        }

        // write K-split partials
        {
            float* pp = g_part[ks];
#pragma unroll
            for (int m = 0; m < 8; m++) {
                int row = ty * 8 + m;
                size_t base = (size_t)row * 4096 + ct * 256 + tx * 8;
                float2 v0 = unpack2(acc[m][0]), v1 = unpack2(acc[m][1]);
                float2 v2 = unpack2(acc[m][2]), v3 = unpack2(acc[m][3]);
                float4 w0 = {v0.x, v0.y, v1.x, v1.y};
                float4 w1 = {v2.x, v2.y, v3.x, v3.y};
                *(float4*)(pp + base + 0) = w0;
                *(float4*)(pp + base + 4) = w1;
            }
        }

        grid_sync();

        // phase 2: reduce partials + Xg, LSTM update
#pragma unroll
        for (int r = 0; r < 2; r++) {
            int idx = bx * 512 + r * 256 + tid;       // 0..65535
            int b_ = idx >> 10;
            int l = idx & 1023;
            int gidx = b_ * 4096 + l;
            float gf = 0.f, gi = 0.f, go = 0.f, gg = 0.f;
#pragma unroll
            for (int s = 0; s < 8; s++) {
                const float* p = g_part[s] + gidx;
                gf += p[0];
                gi += p[1024];
                go += p[2048];
                gg += p[3072];
            }
            const float* xg = g_Xg + (size_t)t * BG + gidx;
            gf += xg[0];
            gi += xg[1024];
            go += xg[2048];
            gg += xg[3072];

            float f = sigm_f(gf);
            float i = sigm_f(gi);
            float o = sigm_f(go);
            float g = tanh_f(gg);

            float c = fmaf(f, g_c[idx], i * g);
            float hn = o * tanh_f(c);

            g_c[idx] = c;
            g_h[cur ^ 1][idx] = hn;
            out[(size_t)t * BL + idx] = hn;
        }

        grid_sync();
    }
}

// ---------------- launch ----------------
extern "C" void kernel_launch(void* const* d_in, const int* in_sizes, int n_in,
                              void* d_out, int out_size) {
    const float* x  = (const float*)d_in[0];
    const float* Wf = (const float*)d_in[1];
    const float* bf = (const float*)d_in[2];
    const float* Wi = (const float*)d_in[3];
    const float* bi = (const float*)d_in[4];
    const float* Wo = (const float*)d_in[5];
    const float* bo = (const float*)d_in[6];
    const float* Wg = (const float*)d_in[7];
    const float* bg = (const float*)d_in[8];
    float* out = (float*)d_out;

    pack_weights<<<256, 256>>>(Wf, Wi, Wo, Wg, bf, bi, bo, bg);
    init_state<<<256, 256>>>();
    gemm_x<<<dim3(32, 256), 256>>>(x);
    lstm_scan<<<NBLK, 256>>>(out);
}

// round 6
// speedup vs baseline: 2.1141x; 2.1141x over previous
#include <cuda_runtime.h>
#include <cuda_bf16.h>
#include <stdint.h>

// ---------------- dims ----------------
#define T_STEPS 512
#define BL      65536
#define NBLK    128

// scan smem (pitch 528 = 256 bf16 + 16B pad)
#define S_WHI 0
#define S_WLO 67584
#define S_AHI 135168
#define S_ALO 168960
#define SCAN_SMEM 202752

// gemm_x smem (pitch 272 = 128 bf16 + 16B pad)
#define X_AHI 0
#define X_ALO 34816
#define X_BHI 69632
#define X_BLO 104448
#define GX_SMEM 139264

// ---------------- scratch ----------------
__device__ __nv_bfloat16 g_Wxh[4096u * 1024u];   // Wx^T [j][k] hi
__device__ __nv_bfloat16 g_Wxl[4096u * 1024u];   // lo
__device__ __nv_bfloat16 g_Whh[4096u * 1024u];   // Wh^T [j][k] hi
__device__ __nv_bfloat16 g_Whl[4096u * 1024u];
__device__ float         g_bias[4096];
__device__ __nv_bfloat16 g_Xhi[33554432u];       // x split [32768][1024]
__device__ __nv_bfloat16 g_Xlo[33554432u];
__device__ float         g_Xg[(size_t)T_STEPS * 262144u]; // x-proj + bias [row][4096]
__device__ __nv_bfloat16 g_Hhi[2][BL];           // h [b][l] hi/lo, double buffered
__device__ __nv_bfloat16 g_Hlo[2][BL];
__device__ float         g_c[BL];
__device__ float         g_part[4u * 64u * 4096u]; // [ks][b][j]
__device__ unsigned int  g_bar_count = 0;
__device__ volatile unsigned int g_bar_gen = 0;

// ---------------- helpers ----------------
__device__ __forceinline__ uint32_t smem_u32(const void* p) {
    uint32_t a;
    asm("{ .reg .u64 t; cvta.to.shared.u64 t, %1; cvt.u32.u64 %0, t; }" : "=r"(a) : "l"(p));
    return a;
}
__device__ __forceinline__ void ldsm4(uint32_t* r, uint32_t addr) {
    asm volatile("ldmatrix.sync.aligned.m8n8.x4.shared.b16 {%0,%1,%2,%3}, [%4];"
                 : "=r"(r[0]), "=r"(r[1]), "=r"(r[2]), "=r"(r[3]) : "r"(addr));
}
__device__ __forceinline__ void mma_bf16(float* d, const uint32_t* a, uint32_t b0, uint32_t b1) {
    asm volatile("mma.sync.aligned.m16n8k16.row.col.f32.bf16.bf16.f32 "
                 "{%0,%1,%2,%3}, {%4,%5,%6,%7}, {%8,%9}, {%0,%1,%2,%3};"
                 : "+f"(d[0]), "+f"(d[1]), "+f"(d[2]), "+f"(d[3])
                 : "r"(a[0]), "r"(a[1]), "r"(a[2]), "r"(a[3]), "r"(b0), "r"(b1));
}
// A fragment address (row-major m16k16), pitch P bytes
__device__ __forceinline__ uint32_t addrA(uint32_t base, int P, int row0, int kbyte, int lane) {
    int arow = (lane & 7) + ((lane >> 3) & 1) * 8;
    int acol = lane >> 4;
    return base + (uint32_t)((row0 + arow) * P + acol * 16 + kbyte);
}
// B fragment address (col-major k16 x n16 via x4 -> two n8 frags), pitch P bytes
__device__ __forceinline__ uint32_t addrB(uint32_t base, int P, int col0, int kbyte, int lane) {
    int bcol = (lane & 7) + (lane >> 4) * 8;
    int bk = ((lane >> 3) & 1) * 16;
    return base + (uint32_t)((col0 + bcol) * P + kbyte + bk);
}

__device__ __forceinline__ float sigm_f(float x) { return __fdividef(1.f, 1.f + __expf(-x)); }
__device__ __forceinline__ float tanh_f(float x) { return __fdividef(2.f, 1.f + __expf(-2.f * x)) - 1.f; }

// ---------------- grid barrier ----------------
__device__ __forceinline__ void grid_sync() {
    __threadfence();
    __syncthreads();
    if (threadIdx.x == 0) {
        unsigned int gen = g_bar_gen;
        if (atomicAdd(&g_bar_count, 1u) == NBLK - 1) {
            g_bar_count = 0;
            __threadfence();
            g_bar_gen = gen + 1;
        } else {
            while (g_bar_gen == gen) { __nanosleep(32); }
        }
    }
    __syncthreads();
    __threadfence();
}

// ---------------- prep ----------------
__global__ void prep_weights(const float* __restrict__ Wf, const float* __restrict__ Wi,
                             const float* __restrict__ Wo, const float* __restrict__ Wg,
                             const float* __restrict__ bf, const float* __restrict__ bi,
                             const float* __restrict__ bo, const float* __restrict__ bg) {
    unsigned st = gridDim.x * blockDim.x;
    unsigned t0 = blockIdx.x * blockDim.x + threadIdx.x;
    for (unsigned i = t0; i < 4096u * 1024u; i += st) {
        unsigned j = i >> 10, k = i & 1023;
        unsigned g = j >> 10, l = j & 1023;
        const float* W = (g == 0) ? Wf : (g == 1) ? Wi : (g == 2) ? Wo : Wg;
        float vx = W[k * 1024 + l];
        float vh = W[(1024 + k) * 1024 + l];
        __nv_bfloat16 hx = __float2bfloat16(vx);
        __nv_bfloat16 hh = __float2bfloat16(vh);
        g_Wxh[i] = hx; g_Wxl[i] = __float2bfloat16(vx - __bfloat162float(hx));
        g_Whh[i] = hh; g_Whl[i] = __float2bfloat16(vh - __bfloat162float(hh));
    }
    for (unsigned i = t0; i < 4096u; i += st) {
        unsigned g = i >> 10, l = i & 1023;
        const float* b = (g == 0) ? bf : (g == 1) ? bi : (g == 2) ? bo : bg;
        g_bias[i] = b[l];
    }
}

__global__ void split_x(const float* __restrict__ x) {
    unsigned st = gridDim.x * blockDim.x;
    for (unsigned i = blockIdx.x * blockDim.x + threadIdx.x; i < 33554432u; i += st) {
        float v = x[i];
        __nv_bfloat16 hi = __float2bfloat16(v);
        g_Xhi[i] = hi;
        g_Xlo[i] = __float2bfloat16(v - __bfloat162float(hi));
    }
}

__global__ void init_state() {
    int i = blockIdx.x * blockDim.x + threadIdx.x;
    if (i < BL) {
        g_c[i] = 0.f;
        __nv_bfloat16 z = __float2bfloat16(0.f);
        g_Hhi[0][i] = z; g_Hhi[1][i] = z;
        g_Hlo[0][i] = z; g_Hlo[1][i] = z;
    }
}

// ---------------- gemm_x: Xg = x @ Wx + bias ----------------
// CTA tile m128 x n128, K=1024 in 8 chunks of 128. 8 warps (2m x 4n), warp m64n32.
// grid: (x = 32 n-tiles  [fast -> all of W resident in L2], y = 256 m-tiles)
__global__ __launch_bounds__(256, 1) void gemm_x() {
    extern __shared__ char smraw[];
    uint32_t base = smem_u32(smraw);
    char* sm = smraw;
    const int tid = threadIdx.x, lane = tid & 31, wid = tid >> 5;
    const int wm = wid & 1, wn = wid >> 1;
    const int ntile = blockIdx.x, mtile = blockIdx.y;
    const int m0 = mtile * 128, n0 = ntile * 128;

    float acc[4][4][4];
#pragma unroll
    for (int a = 0; a < 4; a++)
#pragma unroll
        for (int b = 0; b < 4; b++)
#pragma unroll
            for (int c = 0; c < 4; c++) acc[a][b][c] = 0.f;

    for (int ch = 0; ch < 8; ch++) {
        // load chunk: A rows [m0,+128) k [ch*128,+128); B cols [n0,+128) same k
#pragma unroll
        for (int r8 = 0; r8 < 8; r8++) {
            int i = tid + r8 * 256;          // 0..2047
            int r = i >> 4, c = i & 15;
            size_t srcA = (size_t)(m0 + r) * 1024 + ch * 128 + c * 8;
            size_t srcB = (size_t)(n0 + r) * 1024 + ch * 128 + c * 8;
            uint32_t dst = (uint32_t)(r * 272 + c * 16);
            *(uint4*)(sm + X_AHI + dst) = *(const uint4*)(g_Xhi + srcA);
            *(uint4*)(sm + X_ALO + dst) = *(const uint4*)(g_Xlo + srcA);
            *(uint4*)(sm + X_BHI + dst) = *(const uint4*)(g_Wxh + srcB);
            *(uint4*)(sm + X_BLO + dst) = *(const uint4*)(g_Wxl + srcB);
        }
        __syncthreads();

        for (int kk = 0; kk < 8; kk++) {
            int kb = kk * 32;
            uint32_t ah[4][4], al[4][4], bh[2][4], blo[2][4];
#pragma unroll
            for (int mf = 0; mf < 4; mf++) {
                ldsm4(ah[mf], addrA(base + X_AHI, 272, wm * 64 + mf * 16, kb, lane));
                ldsm4(al[mf], addrA(base + X_ALO, 272, wm * 64 + mf * 16, kb, lane));
            }
#pragma unroll
            for (int g = 0; g < 2; g++) {
                ldsm4(bh[g],  addrB(base + X_BHI, 272, wn * 32 + g * 16, kb, lane));
                ldsm4(blo[g], addrB(base + X_BLO, 272, wn * 32 + g * 16, kb, lane));
            }
#pragma unroll
            for (int mf = 0; mf < 4; mf++)
#pragma unroll
                for (int nf = 0; nf < 4; nf++) {
                    int gg = nf >> 1, pp = (nf & 1) * 2;
                    mma_bf16(acc[mf][nf], ah[mf], bh[gg][pp], bh[gg][pp + 1]);
                    mma_bf16(acc[mf][nf], al[mf], bh[gg][pp], bh[gg][pp + 1]);
                    mma_bf16(acc[mf][nf], ah[mf], blo[gg][pp], blo[gg][pp + 1]);
                }
        }
        __syncthreads();
    }

    // epilogue: + bias -> g_Xg[row][j]
    const int g = lane >> 2, t2 = (lane & 3) * 2;
#pragma unroll
    for (int mf = 0; mf < 4; mf++) {
        int r0 = m0 + wm * 64 + mf * 16 + g;
#pragma unroll
        for (int nf = 0; nf < 4; nf++) {
            int j0 = n0 + wn * 32 + nf * 8 + t2;
            float2 bi = *(const float2*)&g_bias[j0];
            float2 v0 = {acc[mf][nf][0] + bi.x, acc[mf][nf][1] + bi.y};
            float2 v1 = {acc[mf][nf][2] + bi.x, acc[mf][nf][3] + bi.y};
            *(float2*)&g_Xg[(size_t)r0 * 4096 + j0] = v0;
            *(float2*)&g_Xg[(size_t)(r0 + 8) * 4096 + j0] = v1;
        }
    }
}

// ---------------- persistent recurrent scan ----------------
// 128 CTAs: ct = bx>>2 (j-tile of 128), ks = bx&3 (K slice of 256).
// Wh slice (hi+lo) resident in smem all 512 steps. CTA tile m64(b) x n128(j),
// 8 warps (2m x 4n), warp m32n32, 16 k-steps.
__global__ __launch_bounds__(256, 1) void lstm_scan(float* __restrict__ out) {
    extern __shared__ char smraw[];
    uint32_t base = smem_u32(smraw);
    char* sm = smraw;
    const int tid = threadIdx.x, lane = tid & 31, wid = tid >> 5;
    const int wm = wid & 1, wn = wid >> 1;
    const int bx = blockIdx.x, ct = bx >> 2, ks = bx & 3;

    // resident Wh slice: cols j [ct*128,+128), k [ks*256,+256)
#pragma unroll
    for (int r16 = 0; r16 < 16; r16++) {
        int i = tid + r16 * 256;             // 0..4095
        int r = i >> 5, c = i & 31;
        size_t src = (size_t)(ct * 128 + r) * 1024 + ks * 256 + c * 8;
        uint32_t dst = (uint32_t)(r * 528 + c * 16);
        *(uint4*)(sm + S_WHI + dst) = *(const uint4*)(g_Whh + src);
        *(uint4*)(sm + S_WLO + dst) = *(const uint4*)(g_Whl + src);
    }
    __syncthreads();

    const int g = lane >> 2, t2 = (lane & 3) * 2;

    for (int t = 0; t < T_STEPS; t++) {
        const int cur = t & 1;
        const __nv_bfloat16* __restrict__ hh = g_Hhi[cur];
        const __nv_bfloat16* __restrict__ hl = g_Hlo[cur];

        // stage h tile [64 b][256 k]
#pragma unroll
        for (int r8 = 0; r8 < 8; r8++) {
            int i = tid + r8 * 256;          // 0..2047
            int r = i >> 5, c = i & 31;
            size_t src = (size_t)r * 1024 + ks * 256 + c * 8;
            uint32_t dst = (uint32_t)(r * 528 + c * 16);
            *(uint4*)(sm + S_AHI + dst) = *(const uint4*)(hh + src);
            *(uint4*)(sm + S_ALO + dst) = *(const uint4*)(hl + src);
        }
        __syncthreads();

        float acc[2][4][4];
#pragma unroll
        for (int a = 0; a < 2; a++)
#pragma unroll
            for (int b = 0; b < 4; b++)
#pragma unroll
                for (int c = 0; c < 4; c++) acc[a][b][c] = 0.f;

        for (int kk = 0; kk < 16; kk++) {
            int kb = kk * 32;
            uint32_t ah[2][4], al[2][4], bh[2][4], blo[2][4];
#pragma unroll
            for (int mf = 0; mf < 2; mf++) {
                ldsm4(ah[mf], addrA(base + S_AHI, 528, wm * 32 + mf * 16, kb, lane));
                ldsm4(al[mf], addrA(base + S_ALO, 528, wm * 32 + mf * 16, kb, lane));
            }
#pragma unroll
            for (int gg = 0; gg < 2; gg++) {
                ldsm4(bh[gg],  addrB(base + S_WHI, 528, wn * 32 + gg * 16, kb, lane));
                ldsm4(blo[gg], addrB(base + S_WLO, 528, wn * 32 + gg * 16, kb, lane));
            }
#pragma unroll
            for (int mf = 0; mf < 2; mf++)
#pragma unroll
                for (int nf = 0; nf < 4; nf++) {
                    int gg = nf >> 1, pp = (nf & 1) * 2;
                    mma_bf16(acc[mf][nf], ah[mf], bh[gg][pp], bh[gg][pp + 1]);
                    mma_bf16(acc[mf][nf], al[mf], bh[gg][pp], bh[gg][pp + 1]);
                    mma_bf16(acc[mf][nf], ah[mf], blo[gg][pp], blo[gg][pp + 1]);
                }
        }
        __syncthreads();   // smem A reuse next step

        // write partials: g_part[ks][b][j]
#pragma unroll
        for (int mf = 0; mf < 2; mf++) {
            int b0 = wm * 32 + mf * 16 + g;
#pragma unroll
            for (int nf = 0; nf < 4; nf++) {
                int j0 = ct * 128 + wn * 32 + nf * 8 + t2;
                *(float2*)&g_part[(size_t)(ks * 64 + b0) * 4096 + j0] =
                    make_float2(acc[mf][nf][0], acc[mf][nf][1]);
                *(float2*)&g_part[(size_t)(ks * 64 + b0 + 8) * 4096 + j0] =
                    make_float2(acc[mf][nf][2], acc[mf][nf][3]);
            }
        }

        grid_sync();

        // phase 2: reduce partials + Xg, LSTM pointwise update
#pragma unroll
        for (int r2 = 0; r2 < 2; r2++) {
            int idx = bx * 512 + r2 * 256 + tid;    // 0..65535
            int b = idx >> 10, l = idx & 1023;
            int gidx = (b << 12) + l;
            float gf = 0.f, gi = 0.f, go = 0.f, gg2 = 0.f;
#pragma unroll
            for (int s = 0; s < 4; s++) {
                const float* p = g_part + (size_t)s * 262144 + gidx;
                gf += p[0];
                gi += p[1024];
                go += p[2048];
                gg2 += p[3072];
            }
            const float* xg = g_Xg + (size_t)(t * 64 + b) * 4096 + l;
            gf += xg[0];
            gi += xg[1024];
            go += xg[2048];
            gg2 += xg[3072];

            float f = sigm_f(gf);
            float i = sigm_f(gi);
            float o = sigm_f(go);
            float gv = tanh_f(gg2);

            float c = fmaf(f, g_c[idx], i * gv);
            float hn = o * tanh_f(c);

            g_c[idx] = c;
            out[(size_t)t * BL + idx] = hn;
            __nv_bfloat16 hb = __float2bfloat16(hn);
            g_Hhi[cur ^ 1][idx] = hb;
            g_Hlo[cur ^ 1][idx] = __float2bfloat16(hn - __bfloat162float(hb));
        }

        grid_sync();
    }
}

// ---------------- launch ----------------
extern "C" void kernel_launch(void* const* d_in, const int* in_sizes, int n_in,
                              void* d_out, int out_size) {
    const float* x  = (const float*)d_in[0];
    const float* Wf = (const float*)d_in[1];
    const float* bf = (const float*)d_in[2];
    const float* Wi = (const float*)d_in[3];
    const float* bi = (const float*)d_in[4];
    const float* Wo = (const float*)d_in[5];
    const float* bo = (const float*)d_in[6];
    const float* Wg = (const float*)d_in[7];
    const float* bg = (const float*)d_in[8];
    float* out = (float*)d_out;

    cudaFuncSetAttribute(gemm_x, cudaFuncAttributeMaxDynamicSharedMemorySize, GX_SMEM);
    cudaFuncSetAttribute(lstm_scan, cudaFuncAttributeMaxDynamicSharedMemorySize, SCAN_SMEM);

    prep_weights<<<512, 256>>>(Wf, Wi, Wo, Wg, bf, bi, bo, bg);
    split_x<<<1024, 256>>>(x);
    init_state<<<256, 256>>>();
    gemm_x<<<dim3(32, 256), 256, GX_SMEM>>>();
    lstm_scan<<<NBLK, 256, SCAN_SMEM>>>(out);
}

// round 7
// speedup vs baseline: 2.5845x; 1.2225x over previous
#include <cuda_runtime.h>
#include <cuda_bf16.h>
#include <stdint.h>

// ---------------- dims ----------------
#define T_STEPS 512
#define BL      65536
#define NBLK    128

// scan smem (pitch 528 = 256 bf16 + 16B pad)
#define S_WHI 0
#define S_WLO 67584
#define S_AHI 135168
#define S_ALO 168960
#define SCAN_SMEM 202752

// gemm_x smem (pitch 272 = 128 bf16 + 16B pad)
#define X_AHI 0
#define X_ALO 34816
#define X_BHI 69632
#define X_BLO 104448
#define GX_SMEM 139264

// ---------------- scratch ----------------
__device__ __nv_bfloat16 g_Wxh[4096u * 1024u];   // Wx^T [j][k] hi
__device__ __nv_bfloat16 g_Wxl[4096u * 1024u];   // lo
__device__ __nv_bfloat16 g_Whh[4096u * 1024u];   // Wh^T [j][k] hi
__device__ __nv_bfloat16 g_Whl[4096u * 1024u];
__device__ float         g_bias[4096];
__device__ __nv_bfloat16 g_Xhi[33554432u];       // x split [32768][1024]
__device__ __nv_bfloat16 g_Xlo[33554432u];
__device__ float         g_Xg[(size_t)T_STEPS * 262144u]; // x-proj + bias [row][4096]
__device__ __nv_bfloat16 g_Hhi[2][BL];           // h [b][l] hi/lo, double buffered
__device__ __nv_bfloat16 g_Hlo[2][BL];
__device__ float         g_c[BL];
__device__ float         g_part[4u * 64u * 4096u]; // [ks][b][j]
__device__ unsigned int  g_ctr;                   // monotonic barrier counter

// ---------------- helpers ----------------
__device__ __forceinline__ uint32_t smem_u32(const void* p) {
    uint32_t a;
    asm("{ .reg .u64 t; cvta.to.shared.u64 t, %1; cvt.u32.u64 %0, t; }" : "=r"(a) : "l"(p));
    return a;
}
__device__ __forceinline__ void ldsm4(uint32_t* r, uint32_t addr) {
    asm volatile("ldmatrix.sync.aligned.m8n8.x4.shared.b16 {%0,%1,%2,%3}, [%4];"
                 : "=r"(r[0]), "=r"(r[1]), "=r"(r[2]), "=r"(r[3]) : "r"(addr));
}
__device__ __forceinline__ void mma_bf16(float* d, const uint32_t* a, uint32_t b0, uint32_t b1) {
    asm volatile("mma.sync.aligned.m16n8k16.row.col.f32.bf16.bf16.f32 "
                 "{%0,%1,%2,%3}, {%4,%5,%6,%7}, {%8,%9}, {%0,%1,%2,%3};"
                 : "+f"(d[0]), "+f"(d[1]), "+f"(d[2]), "+f"(d[3])
                 : "r"(a[0]), "r"(a[1]), "r"(a[2]), "r"(a[3]), "r"(b0), "r"(b1));
}
// A fragment address (row-major m16k16), pitch P bytes
__device__ __forceinline__ uint32_t addrA(uint32_t base, int P, int row0, int kbyte, int lane) {
    int arow = (lane & 7) + ((lane >> 3) & 1) * 8;
    int acol = lane >> 4;
    return base + (uint32_t)((row0 + arow) * P + acol * 16 + kbyte);
}
// B fragment address (col-major k16 x n16 via x4 -> two n8 frags), pitch P bytes
__device__ __forceinline__ uint32_t addrB(uint32_t base, int P, int col0, int kbyte, int lane) {
    int bcol = (lane & 7) + (lane >> 4) * 8;
    int bk = ((lane >> 3) & 1) * 16;
    return base + (uint32_t)((col0 + bcol) * P + kbyte + bk);
}

__device__ __forceinline__ float sigm_f(float x) { return __fdividef(1.f, 1.f + __expf(-x)); }
__device__ __forceinline__ float tanh_f(float x) { return __fdividef(2.f, 1.f + __expf(-2.f * x)) - 1.f; }

// ---------------- split grid barrier (release/acquire, monotonic counter) ----------------
// hb chain: writers' stores -> bar.sync -> t0 red.release -> peer t0 ld.acquire -> bar.sync -> readers.
__device__ __forceinline__ void bar_arrive() {
    __syncthreads();
    if (threadIdx.x == 0)
        asm volatile("red.release.gpu.add.u32 [%0], 1;" :: "l"(&g_ctr) : "memory");
}
__device__ __forceinline__ void bar_wait(unsigned int target) {
    if (threadIdx.x == 0) {
        unsigned int v;
        do {
            asm volatile("ld.acquire.gpu.u32 %0, [%1];" : "=r"(v) : "l"(&g_ctr) : "memory");
        } while (v < target);
    }
    __syncthreads();
}

// ---------------- prep ----------------
__global__ void prep_weights(const float* __restrict__ Wf, const float* __restrict__ Wi,
                             const float* __restrict__ Wo, const float* __restrict__ Wg,
                             const float* __restrict__ bf, const float* __restrict__ bi,
                             const float* __restrict__ bo, const float* __restrict__ bg) {
    unsigned st = gridDim.x * blockDim.x;
    unsigned t0 = blockIdx.x * blockDim.x + threadIdx.x;
    for (unsigned i = t0; i < 4096u * 1024u; i += st) {
        unsigned j = i >> 10, k = i & 1023;
        unsigned g = j >> 10, l = j & 1023;
        const float* W = (g == 0) ? Wf : (g == 1) ? Wi : (g == 2) ? Wo : Wg;
        float vx = W[k * 1024 + l];
        float vh = W[(1024 + k) * 1024 + l];
        __nv_bfloat16 hx = __float2bfloat16(vx);
        __nv_bfloat16 hh = __float2bfloat16(vh);
        g_Wxh[i] = hx; g_Wxl[i] = __float2bfloat16(vx - __bfloat162float(hx));
        g_Whh[i] = hh; g_Whl[i] = __float2bfloat16(vh - __bfloat162float(hh));
    }
    for (unsigned i = t0; i < 4096u; i += st) {
        unsigned g = i >> 10, l = i & 1023;
        const float* b = (g == 0) ? bf : (g == 1) ? bi : (g == 2) ? bo : bg;
        g_bias[i] = b[l];
    }
}

__global__ void split_x(const float* __restrict__ x) {
    unsigned st = gridDim.x * blockDim.x;
    for (unsigned i = blockIdx.x * blockDim.x + threadIdx.x; i < 33554432u; i += st) {
        float v = x[i];
        __nv_bfloat16 hi = __float2bfloat16(v);
        g_Xhi[i] = hi;
        g_Xlo[i] = __float2bfloat16(v - __bfloat162float(hi));
    }
}

__global__ void init_state() {
    int i = blockIdx.x * blockDim.x + threadIdx.x;
    if (i == 0) g_ctr = 0;    // reset barrier counter every launch (graph replays!)
    if (i < BL) {
        g_c[i] = 0.f;
        __nv_bfloat16 z = __float2bfloat16(0.f);
        g_Hhi[0][i] = z; g_Hhi[1][i] = z;
        g_Hlo[0][i] = z; g_Hlo[1][i] = z;
    }
}

// ---------------- gemm_x: Xg = x @ Wx + bias ----------------
// CTA tile m128 x n128, K=1024 in 8 chunks of 128. 16 warps (4m x 4n), warp m32n32.
// grid: (x = 32 n-tiles, y = 256 m-tiles)
__global__ __launch_bounds__(512, 1) void gemm_x() {
    extern __shared__ char smraw[];
    uint32_t base = smem_u32(smraw);
    char* sm = smraw;
    const int tid = threadIdx.x, lane = tid & 31, wid = tid >> 5;
    const int wm = wid & 3, wn = wid >> 2;
    const int ntile = blockIdx.x, mtile = blockIdx.y;
    const int m0 = mtile * 128, n0 = ntile * 128;

    float acc[2][4][4];
#pragma unroll
    for (int a = 0; a < 2; a++)
#pragma unroll
        for (int b = 0; b < 4; b++)
#pragma unroll
            for (int c = 0; c < 4; c++) acc[a][b][c] = 0.f;

    for (int ch = 0; ch < 8; ch++) {
#pragma unroll
        for (int r8 = 0; r8 < 4; r8++) {
            int i = tid + r8 * 512;          // 0..2047
            int r = i >> 4, c = i & 15;
            size_t srcA = (size_t)(m0 + r) * 1024 + ch * 128 + c * 8;
            size_t srcB = (size_t)(n0 + r) * 1024 + ch * 128 + c * 8;
            uint32_t dst = (uint32_t)(r * 272 + c * 16);
            *(uint4*)(sm + X_AHI + dst) = *(const uint4*)(g_Xhi + srcA);
            *(uint4*)(sm + X_ALO + dst) = *(const uint4*)(g_Xlo + srcA);
            *(uint4*)(sm + X_BHI + dst) = *(const uint4*)(g_Wxh + srcB);
            *(uint4*)(sm + X_BLO + dst) = *(const uint4*)(g_Wxl + srcB);
        }
        __syncthreads();

        for (int kk = 0; kk < 8; kk++) {
            int kb = kk * 32;
            uint32_t ah[2][4], al[2][4], bh[2][4], blo[2][4];
#pragma unroll
            for (int mf = 0; mf < 2; mf++) {
                ldsm4(ah[mf], addrA(base + X_AHI, 272, wm * 32 + mf * 16, kb, lane));
                ldsm4(al[mf], addrA(base + X_ALO, 272, wm * 32 + mf * 16, kb, lane));
            }
#pragma unroll
            for (int g = 0; g < 2; g++) {
                ldsm4(bh[g],  addrB(base + X_BHI, 272, wn * 32 + g * 16, kb, lane));
                ldsm4(blo[g], addrB(base + X_BLO, 272, wn * 32 + g * 16, kb, lane));
            }
#pragma unroll
            for (int mf = 0; mf < 2; mf++)
#pragma unroll
                for (int nf = 0; nf < 4; nf++) {
                    int gg = nf >> 1, pp = (nf & 1) * 2;
                    mma_bf16(acc[mf][nf], ah[mf], bh[gg][pp], bh[gg][pp + 1]);
                    mma_bf16(acc[mf][nf], al[mf], bh[gg][pp], bh[gg][pp + 1]);
                    mma_bf16(acc[mf][nf], ah[mf], blo[gg][pp], blo[gg][pp + 1]);
                }
        }
        __syncthreads();
    }

    // epilogue: + bias -> g_Xg[row][j]
    const int g = lane >> 2, t2 = (lane & 3) * 2;
#pragma unroll
    for (int mf = 0; mf < 2; mf++) {
        int r0 = m0 + wm * 32 + mf * 16 + g;
#pragma unroll
        for (int nf = 0; nf < 4; nf++) {
            int j0 = n0 + wn * 32 + nf * 8 + t2;
            float2 bi = *(const float2*)&g_bias[j0];
            float2 v0 = {acc[mf][nf][0] + bi.x, acc[mf][nf][1] + bi.y};
            float2 v1 = {acc[mf][nf][2] + bi.x, acc[mf][nf][3] + bi.y};
            *(float2*)&g_Xg[(size_t)r0 * 4096 + j0] = v0;
            *(float2*)&g_Xg[(size_t)(r0 + 8) * 4096 + j0] = v1;
        }
    }
}

// ---------------- persistent recurrent scan ----------------
// 128 CTAs: ct = bx>>2 (j-tile of 128), ks = bx&3 (K slice of 256).
// Wh slice (hi+lo) resident in smem all 512 steps. CTA tile m64(b) x n128(j),
// 8 warps (2m x 4n), warp m32n32, 16 k-steps.
__global__ __launch_bounds__(256, 1) void lstm_scan(float* __restrict__ out) {
    extern __shared__ char smraw[];
    uint32_t base = smem_u32(smraw);
    char* sm = smraw;
    const int tid = threadIdx.x, lane = tid & 31, wid = tid >> 5;
    const int wm = wid & 1, wn = wid >> 1;
    const int bx = blockIdx.x, ct = bx >> 2, ks = bx & 3;

    // resident Wh slice: cols j [ct*128,+128), k [ks*256,+256)
#pragma unroll
    for (int r16 = 0; r16 < 16; r16++) {
        int i = tid + r16 * 256;             // 0..4095
        int r = i >> 5, c = i & 31;
        size_t src = (size_t)(ct * 128 + r) * 1024 + ks * 256 + c * 8;
        uint32_t dst = (uint32_t)(r * 528 + c * 16);
        *(uint4*)(sm + S_WHI + dst) = *(const uint4*)(g_Whh + src);
        *(uint4*)(sm + S_WLO + dst) = *(const uint4*)(g_Whl + src);
    }
    __syncthreads();

    const int g = lane >> 2, t2 = (lane & 3) * 2;
    unsigned int nbar = 0;

    for (int t = 0; t < T_STEPS; t++) {
        const int cur = t & 1;
        const __nv_bfloat16* __restrict__ hh = g_Hhi[cur];
        const __nv_bfloat16* __restrict__ hl = g_Hlo[cur];

        // stage h tile [64 b][256 k]
#pragma unroll
        for (int r8 = 0; r8 < 8; r8++) {
            int i = tid + r8 * 256;          // 0..2047
            int r = i >> 5, c = i & 31;
            size_t src = (size_t)r * 1024 + ks * 256 + c * 8;
            uint32_t dst = (uint32_t)(r * 528 + c * 16);
            *(uint4*)(sm + S_AHI + dst) = *(const uint4*)(hh + src);
            *(uint4*)(sm + S_ALO + dst) = *(const uint4*)(hl + src);
        }
        __syncthreads();

        float acc[2][4][4];
#pragma unroll
        for (int a = 0; a < 2; a++)
#pragma unroll
            for (int b = 0; b < 4; b++)
#pragma unroll
                for (int c = 0; c < 4; c++) acc[a][b][c] = 0.f;

        for (int kk = 0; kk < 16; kk++) {
            int kb = kk * 32;
            uint32_t ah[2][4], al[2][4], bh[2][4], blo[2][4];
#pragma unroll
            for (int mf = 0; mf < 2; mf++) {
                ldsm4(ah[mf], addrA(base + S_AHI, 528, wm * 32 + mf * 16, kb, lane));
                ldsm4(al[mf], addrA(base + S_ALO, 528, wm * 32 + mf * 16, kb, lane));
            }
#pragma unroll
            for (int gg = 0; gg < 2; gg++) {
                ldsm4(bh[gg],  addrB(base + S_WHI, 528, wn * 32 + gg * 16, kb, lane));
                ldsm4(blo[gg], addrB(base + S_WLO, 528, wn * 32 + gg * 16, kb, lane));
            }
#pragma unroll
            for (int mf = 0; mf < 2; mf++)
#pragma unroll
                for (int nf = 0; nf < 4; nf++) {
                    int gg = nf >> 1, pp = (nf & 1) * 2;
                    mma_bf16(acc[mf][nf], ah[mf], bh[gg][pp], bh[gg][pp + 1]);
                    mma_bf16(acc[mf][nf], al[mf], bh[gg][pp], bh[gg][pp + 1]);
                    mma_bf16(acc[mf][nf], ah[mf], blo[gg][pp], blo[gg][pp + 1]);
                }
        }

        // write partials: g_part[ks][b][j]
#pragma unroll
        for (int mf = 0; mf < 2; mf++) {
            int b0 = wm * 32 + mf * 16 + g;
#pragma unroll
            for (int nf = 0; nf < 4; nf++) {
                int j0 = ct * 128 + wn * 32 + nf * 8 + t2;
                *(float2*)&g_part[(size_t)(ks * 64 + b0) * 4096 + j0] =
                    make_float2(acc[mf][nf][0], acc[mf][nf][1]);
                *(float2*)&g_part[(size_t)(ks * 64 + b0 + 8) * 4096 + j0] =
                    make_float2(acc[mf][nf][2], acc[mf][nf][3]);
            }
        }

        bar_arrive();
        // prefetch phase-2 operands in the barrier gap (Xg const; c thread-owned)
        float pxg[2][4], pc[2];
        int pidx[2];
#pragma unroll
        for (int r2 = 0; r2 < 2; r2++) {
            int idx = bx * 512 + r2 * 256 + tid;
            pidx[r2] = idx;
            int b = idx >> 10, l = idx & 1023;
            const float* xg = g_Xg + (size_t)(t * 64 + b) * 4096 + l;
            pxg[r2][0] = xg[0];
            pxg[r2][1] = xg[1024];
            pxg[r2][2] = xg[2048];
            pxg[r2][3] = xg[3072];
            pc[r2] = g_c[idx];
        }
        bar_wait(++nbar * NBLK);

        // phase 2: reduce partials + Xg, LSTM pointwise update
#pragma unroll
        for (int r2 = 0; r2 < 2; r2++) {
            int idx = pidx[r2];
            int b = idx >> 10, l = idx & 1023;
            int gidx = (b << 12) + l;
            float gf = pxg[r2][0], gi = pxg[r2][1], go = pxg[r2][2], gg2 = pxg[r2][3];
#pragma unroll
            for (int s = 0; s < 4; s++) {
                const float* p = g_part + (size_t)s * 262144 + gidx;
                gf += p[0];
                gi += p[1024];
                go += p[2048];
                gg2 += p[3072];
            }

            float f = sigm_f(gf);
            float i = sigm_f(gi);
            float o = sigm_f(go);
            float gv = tanh_f(gg2);

            float c = fmaf(f, pc[r2], i * gv);
            float hn = o * tanh_f(c);

            g_c[idx] = c;
            out[(size_t)t * BL + idx] = hn;
            __nv_bfloat16 hb = __float2bfloat16(hn);
            g_Hhi[cur ^ 1][idx] = hb;
            g_Hlo[cur ^ 1][idx] = __float2bfloat16(hn - __bfloat162float(hb));
        }

        bar_arrive();
        bar_wait(++nbar * NBLK);
    }
}

// ---------------- launch ----------------
extern "C" void kernel_launch(void* const* d_in, const int* in_sizes, int n_in,
                              void* d_out, int out_size) {
    const float* x  = (const float*)d_in[0];
    const float* Wf = (const float*)d_in[1];
    const float* bf = (const float*)d_in[2];
    const float* Wi = (const float*)d_in[3];
    const float* bi = (const float*)d_in[4];
    const float* Wo = (const float*)d_in[5];
    const float* bo = (const float*)d_in[6];
    const float* Wg = (const float*)d_in[7];
    const float* bg = (const float*)d_in[8];
    float* out = (float*)d_out;

    cudaFuncSetAttribute(gemm_x, cudaFuncAttributeMaxDynamicSharedMemorySize, GX_SMEM);
    cudaFuncSetAttribute(lstm_scan, cudaFuncAttributeMaxDynamicSharedMemorySize, SCAN_SMEM);

    prep_weights<<<512, 256>>>(Wf, Wi, Wo, Wg, bf, bi, bo, bg);
    split_x<<<1024, 256>>>(x);
    init_state<<<256, 256>>>();
    gemm_x<<<dim3(32, 256), 512, GX_SMEM>>>();
    lstm_scan<<<NBLK, 256, SCAN_SMEM>>>(out);
}